// round 10
// baseline (speedup 1.0000x reference)
#include <cuda_runtime.h>
#include <cuda_bf16.h>

#define HID 4096
#define MH 16384             // 4 * HIDDEN
#define TOK 4
#define NT 512
#define NWARP (NT / 32)      // 16
#define NK 8                 // phase-1 float4-iterations per token
#define F4H (HID / 4)        // 1024 float4 per hidden row

__device__ __forceinline__ float bflo(unsigned u) {   // low bf16 -> f32
    return __uint_as_float(u << 16);
}
__device__ __forceinline__ float bfhi(unsigned u) {   // high bf16 -> f32
    return __uint_as_float(u & 0xFFFF0000u);
}
// round fp32 pair -> packed bf16x2 (RN, matches astype(bfloat16))
__device__ __forceinline__ unsigned pack_bf2(float a, float b) {
    __nv_bfloat162 p = __floats2bfloat162_rn(a, b);
    return *reinterpret_cast<unsigned*>(&p);
}

// one phase-2 chunk: token t, h-group g of tile with base token ptok0,
// weights w[4]; each thread handles ONE float4 of hidden dim.
__device__ __forceinline__ void phase2_chunk(
    const float4* __restrict__ x4, float* __restrict__ out,
    size_t ptok0, int t, int g, int tid, const float* w)
{
    const int h4 = tid + g * NT;                       // float4 idx in hidden
    const float4* xp = x4 + (ptok0 + t) * (MH / 4);
    float4 a = __ldcs(xp + 0 * F4H + h4);
    float4 b = __ldcs(xp + 1 * F4H + h4);
    float4 c = __ldcs(xp + 2 * F4H + h4);
    float4 d = __ldcs(xp + 3 * F4H + h4);
    const float w0 = w[0], w1 = w[1], w2 = w[2], w3 = w[3];

    unsigned qa0 = pack_bf2(a.x, a.y), qa1 = pack_bf2(a.z, a.w);
    unsigned qb0 = pack_bf2(b.x, b.y), qb1 = pack_bf2(b.z, b.w);
    unsigned qc0 = pack_bf2(c.x, c.y), qc1 = pack_bf2(c.z, c.w);
    unsigned qd0 = pack_bf2(d.x, d.y), qd1 = pack_bf2(d.z, d.w);

    float4 r;
    r.x = w0 * bflo(qa0) + w1 * bflo(qb0) + w2 * bflo(qc0) + w3 * bflo(qd0);
    r.y = w0 * bfhi(qa0) + w1 * bfhi(qb0) + w2 * bfhi(qc0) + w3 * bfhi(qd0);
    r.z = w0 * bflo(qa1) + w1 * bflo(qb1) + w2 * bflo(qc1) + w3 * bflo(qd1);
    r.w = w0 * bfhi(qa1) + w1 * bfhi(qb1) + w2 * bfhi(qc1) + w3 * bfhi(qd1);

    __stcs(reinterpret_cast<float4*>(out + (ptok0 + t) * HID) + h4, r);
}

__global__ __launch_bounds__(NT, 2) void hchead_kernel(
    const float* __restrict__ x,
    const float* __restrict__ fn,
    const float* __restrict__ scale,
    const float* __restrict__ base,
    float* __restrict__ out,
    int ntiles)
{
    __shared__ float red[NWARP * 20];
    __shared__ float wsh[2][TOK * 4];    // double-buffered mixing weights

    const int tid  = threadIdx.x;
    const int warp = tid >> 5, lane = tid & 31;

    const float4* x4  = reinterpret_cast<const float4*>(x);
    const float4* fn4 = reinterpret_cast<const float4*>(fn);

    int prev_tile = -1;
    int par = 0;                          // wsh slot for THIS tile's w

    for (int tile = blockIdx.x; tile < ntiles; tile += gridDim.x) {
        const size_t tok0  = (size_t)tile * TOK;
        const bool   hp    = (prev_tile >= 0);
        const size_t ptok0 = (size_t)(hp ? prev_tile : 0) * TOK;
        const float* wprev = wsh[par ^ 1];

        float acc[20];
#pragma unroll
        for (int i = 0; i < 20; i++) acc[i] = 0.f;

        // ---- Phase 1 (this tile) interleaved with phase 2 (prev tile) ----
#pragma unroll
        for (int k = 0; k < NK; k++) {
            const int f = tid + k * NT;
            const float4 g0 = fn4[0 * (MH / 4) + f];
            const float4 g1 = fn4[1 * (MH / 4) + f];
            const float4 g2 = fn4[2 * (MH / 4) + f];
            const float4 g3 = fn4[3 * (MH / 4) + f];
            float4 v0 = x4[(tok0 + 0) * (MH / 4) + f];
            float4 v1 = x4[(tok0 + 1) * (MH / 4) + f];
            float4 v2 = x4[(tok0 + 2) * (MH / 4) + f];
            float4 v3 = x4[(tok0 + 3) * (MH / 4) + f];
#pragma unroll
            for (int t = 0; t < TOK; t++) {
                const float4 v = (t == 0) ? v0 : (t == 1) ? v1 : (t == 2) ? v2 : v3;
                const unsigned p0 = pack_bf2(v.x, v.y);
                const unsigned p1 = pack_bf2(v.z, v.w);
                const float x0 = bflo(p0), x1 = bfhi(p0);
                const float x2 = bflo(p1), x3 = bfhi(p1);
                acc[t * 5 + 0] += x0 * x0 + x1 * x1 + x2 * x2 + x3 * x3;
                acc[t * 5 + 1] += x0 * g0.x + x1 * g0.y + x2 * g0.z + x3 * g0.w;
                acc[t * 5 + 2] += x0 * g1.x + x1 * g1.y + x2 * g1.z + x3 * g1.w;
                acc[t * 5 + 3] += x0 * g2.x + x1 * g2.y + x2 * g2.z + x3 * g2.w;
                acc[t * 5 + 4] += x0 * g3.x + x1 * g3.y + x2 * g3.z + x3 * g3.w;
            }
            // phase-2 chunk k of previous tile (8 chunks = 4 tok x 2 groups)
            if (hp)
                phase2_chunk(x4, out, ptok0, k >> 1, k & 1, tid,
                             wprev + (k >> 1) * 4);
        }

        // ---- Block reduction of 20 partials ----
#pragma unroll
        for (int i = 0; i < 20; i++) {
#pragma unroll
            for (int o = 16; o > 0; o >>= 1)
                acc[i] += __shfl_xor_sync(0xffffffffu, acc[i], o);
        }
        if (lane == 0) {
#pragma unroll
            for (int i = 0; i < 20; i++) red[warp * 20 + i] = acc[i];
        }
        __syncthreads();

        if (tid < TOK) {
            const int t = tid;
            float ss = 0.f, d0 = 0.f, d1 = 0.f, d2 = 0.f, d3 = 0.f;
#pragma unroll
            for (int w = 0; w < NWARP; w++) {
                ss += red[w * 20 + t * 5 + 0];
                d0 += red[w * 20 + t * 5 + 1];
                d1 += red[w * 20 + t * 5 + 2];
                d2 += red[w * 20 + t * 5 + 3];
                d3 += red[w * 20 + t * 5 + 4];
            }
            const float inv = 1.0f / sqrtf(ss * (1.0f / MH) + 1e-6f);
            const float s = scale[0];
            const float a0 = s * (d0 * inv) + base[0];
            const float a1 = s * (d1 * inv) + base[1];
            const float a2 = s * (d2 * inv) + base[2];
            const float a3 = s * (d3 * inv) + base[3];
            const float idn = 1.0f / (fabsf(a0) + fabsf(a1) + fabsf(a2) + fabsf(a3) + 1e-6f);
            wsh[par][t * 4 + 0] = a0 * idn;
            wsh[par][t * 4 + 1] = a1 * idn;
            wsh[par][t * 4 + 2] = a2 * idn;
            wsh[par][t * 4 + 3] = a3 * idn;
        }
        __syncthreads();

        prev_tile = tile;
        par ^= 1;
    }

    // ---- Drain: phase-2 for the last tile this CTA processed ----
    if (prev_tile >= 0) {
        const size_t ptok0 = (size_t)prev_tile * TOK;
        const float* wprev = wsh[par ^ 1];
#pragma unroll
        for (int c = 0; c < 8; c++)
            phase2_chunk(x4, out, ptok0, c >> 1, c & 1, tid,
                         wprev + (c >> 1) * 4);
    }
}

extern "C" void kernel_launch(void* const* d_in, const int* in_sizes, int n_in,
                              void* d_out, int out_size) {
    const float* x     = (const float*)d_in[0];   // [T, 4*4096] fp32
    const float* fn    = (const float*)d_in[1];   // [4, 16384]  fp32
    const float* scale = (const float*)d_in[2];   // [1]
    const float* base  = (const float*)d_in[3];   // [4]
    float* out = (float*)d_out;                   // [T, 4096] fp32

    const int T = in_sizes[0] / MH;               // 8192
    const int ntiles = T / TOK;                   // 2048

    int nsm = 148;
    cudaDeviceGetAttribute(&nsm, cudaDevAttrMultiProcessorCount, 0);
    int grid = 2 * nsm;
    if (grid > ntiles) grid = ntiles;

    hchead_kernel<<<grid, NT>>>(x, fn, scale, base, out, ntiles);
}

// round 11
// speedup vs baseline: 1.4597x; 1.4597x over previous
#include <cuda_runtime.h>
#include <cuda_bf16.h>

#define HID 4096
#define MH 16384             // 4 * HIDDEN
#define TOK 2
#define NT 256
#define NWARP (NT / 32)      // 8
#define NACC (TOK * 5)       // 10
#define NK (MH / 4 / NT)     // 16 float4-iterations per token
#define F4H (HID / 4)        // 1024

__device__ __forceinline__ float bflo(unsigned u) {   // low bf16 -> f32
    return __uint_as_float(u << 16);
}
__device__ __forceinline__ float bfhi(unsigned u) {   // high bf16 -> f32
    return __uint_as_float(u & 0xFFFF0000u);
}
// round fp32 pair -> packed bf16x2 (RN, matches astype(bfloat16))
__device__ __forceinline__ unsigned pack_bf2(float a, float b) {
    __nv_bfloat162 p = __floats2bfloat162_rn(a, b);
    return *reinterpret_cast<unsigned*>(&p);
}

__global__ __launch_bounds__(NT, 4) void hchead_kernel(
    const float* __restrict__ x,
    const float* __restrict__ fn,
    const float* __restrict__ scale,
    const float* __restrict__ base,
    float* __restrict__ out)
{
    __shared__ float red[NWARP * NACC];
    __shared__ float wsh[TOK * 4];

    const int tid  = threadIdx.x;
    const int warp = tid >> 5, lane = tid & 31;
    const size_t tok0 = (size_t)blockIdx.x * TOK;

    const float4* x4  = reinterpret_cast<const float4*>(x);
    const float4* fn4 = reinterpret_cast<const float4*>(fn);

    // acc: t*5+0 = sum(x^2), t*5+1+m = dot with fn[m]
    float acc[NACC];
#pragma unroll
    for (int i = 0; i < NACC; i++) acc[i] = 0.f;

    // ------- Phase 1: stream x (DRAM) + fn (L2), accumulate sums -------
#pragma unroll
    for (int k = 0; k < NK; k++) {          // 16 iterations
        const int f = tid + k * NT;         // float4 index (j = 4f)
        const float4 g0 = fn4[0 * (MH / 4) + f];
        const float4 g1 = fn4[1 * (MH / 4) + f];
        const float4 g2 = fn4[2 * (MH / 4) + f];
        const float4 g3 = fn4[3 * (MH / 4) + f];
        float4 v0 = x4[(tok0 + 0) * (MH / 4) + f];
        float4 v1 = x4[(tok0 + 1) * (MH / 4) + f];
#pragma unroll
        for (int t = 0; t < TOK; t++) {
            const float4 v = (t == 0) ? v0 : v1;
            const unsigned p0 = pack_bf2(v.x, v.y);
            const unsigned p1 = pack_bf2(v.z, v.w);
            const float x0 = bflo(p0), x1 = bfhi(p0);
            const float x2 = bflo(p1), x3 = bfhi(p1);
            acc[t * 5 + 0] += x0 * x0 + x1 * x1 + x2 * x2 + x3 * x3;
            acc[t * 5 + 1] += x0 * g0.x + x1 * g0.y + x2 * g0.z + x3 * g0.w;
            acc[t * 5 + 2] += x0 * g1.x + x1 * g1.y + x2 * g1.z + x3 * g1.w;
            acc[t * 5 + 3] += x0 * g2.x + x1 * g2.y + x2 * g2.z + x3 * g2.w;
            acc[t * 5 + 4] += x0 * g3.x + x1 * g3.y + x2 * g3.z + x3 * g3.w;
        }
    }

    // ------- Block reduction of partials -------
#pragma unroll
    for (int i = 0; i < NACC; i++) {
#pragma unroll
        for (int o = 16; o > 0; o >>= 1)
            acc[i] += __shfl_xor_sync(0xffffffffu, acc[i], o);
    }
    if (lane == 0) {
#pragma unroll
        for (int i = 0; i < NACC; i++) red[warp * NACC + i] = acc[i];
    }
    __syncthreads();

    if (tid < TOK) {
        const int t = tid;
        float ss = 0.f, d0 = 0.f, d1 = 0.f, d2 = 0.f, d3 = 0.f;
#pragma unroll
        for (int w = 0; w < NWARP; w++) {
            ss += red[w * NACC + t * 5 + 0];
            d0 += red[w * NACC + t * 5 + 1];
            d1 += red[w * NACC + t * 5 + 2];
            d2 += red[w * NACC + t * 5 + 3];
            d3 += red[w * NACC + t * 5 + 4];
        }
        const float inv = 1.0f / sqrtf(ss * (1.0f / MH) + 1e-6f);
        const float s = scale[0];
        const float a0 = s * (d0 * inv) + base[0];
        const float a1 = s * (d1 * inv) + base[1];
        const float a2 = s * (d2 * inv) + base[2];
        const float a3 = s * (d3 * inv) + base[3];
        const float idn = 1.0f / (fabsf(a0) + fabsf(a1) + fabsf(a2) + fabsf(a3) + 1e-6f);
        wsh[t * 4 + 0] = a0 * idn;
        wsh[t * 4 + 1] = a1 * idn;
        wsh[t * 4 + 2] = a2 * idn;
        wsh[t * 4 + 3] = a3 * idn;
    }
    __syncthreads();

    // ------- Phase 2: re-read x (evict-first), re-round, combine, store -------
    // 256 threads, 4096 h/token -> 4 float4 groups per thread per token.
#pragma unroll
    for (int t = 0; t < TOK; t++) {
        const float w0 = wsh[t * 4 + 0], w1 = wsh[t * 4 + 1];
        const float w2 = wsh[t * 4 + 2], w3 = wsh[t * 4 + 3];
        const float4* xp = x4 + (tok0 + t) * (MH / 4);
        float4* op = reinterpret_cast<float4*>(out + (tok0 + t) * HID);
#pragma unroll
        for (int g = 0; g < 4; g++) {
            const int h4 = tid + g * NT;      // float4 idx in hidden dim
            float4 a = __ldcs(xp + 0 * F4H + h4);
            float4 b = __ldcs(xp + 1 * F4H + h4);
            float4 c = __ldcs(xp + 2 * F4H + h4);
            float4 d = __ldcs(xp + 3 * F4H + h4);

            unsigned qa0 = pack_bf2(a.x, a.y), qa1 = pack_bf2(a.z, a.w);
            unsigned qb0 = pack_bf2(b.x, b.y), qb1 = pack_bf2(b.z, b.w);
            unsigned qc0 = pack_bf2(c.x, c.y), qc1 = pack_bf2(c.z, c.w);
            unsigned qd0 = pack_bf2(d.x, d.y), qd1 = pack_bf2(d.z, d.w);

            float4 r;
            r.x = w0 * bflo(qa0) + w1 * bflo(qb0) + w2 * bflo(qc0) + w3 * bflo(qd0);
            r.y = w0 * bfhi(qa0) + w1 * bfhi(qb0) + w2 * bfhi(qc0) + w3 * bfhi(qd0);
            r.z = w0 * bflo(qa1) + w1 * bflo(qb1) + w2 * bflo(qc1) + w3 * bflo(qd1);
            r.w = w0 * bfhi(qa1) + w1 * bfhi(qb1) + w2 * bfhi(qc1) + w3 * bfhi(qd1);

            __stcs(op + h4, r);
        }
    }
}

extern "C" void kernel_launch(void* const* d_in, const int* in_sizes, int n_in,
                              void* d_out, int out_size) {
    const float* x     = (const float*)d_in[0];   // [T, 4*4096] fp32
    const float* fn    = (const float*)d_in[1];   // [4, 16384]  fp32
    const float* scale = (const float*)d_in[2];   // [1]
    const float* base  = (const float*)d_in[3];   // [4]
    float* out = (float*)d_out;                   // [T, 4096] fp32

    const int T = in_sizes[0] / MH;               // 8192
    hchead_kernel<<<T / TOK, NT>>>(x, fn, scale, base, out);
}